// round 1
// baseline (speedup 1.0000x reference)
#include <cuda_runtime.h>

// Problem constants (from reference)
#define BB 16
#define AA 128
#define PP 8192
#define TT 5
#define K_LOG2E 1.4426950408889634f   // log2(e); TEMPERATURE = 1.0
#define LN2F    0.6931471805599453f
#define CLIP    0.3f

#define THREADS 128
#define QPT 2                 // queries per thread
#define QPB (THREADS * QPT)   // 256 queries per block

__device__ __forceinline__ float ex2f_a(float x) {
    float y; asm("ex2.approx.ftz.f32 %0, %1;" : "=f"(y) : "f"(x)); return y;
}
__device__ __forceinline__ float sqrtf_a(float x) {
    float y; asm("sqrt.approx.ftz.f32 %0, %1;" : "=f"(y) : "f"(x)); return y;
}
__device__ __forceinline__ float rcpf_a(float x) {
    float y; asm("rcp.approx.ftz.f32 %0, %1;" : "=f"(y) : "f"(x)); return y;
}
__device__ __forceinline__ float rsqrtf_a(float x) {
    float y; asm("rsqrt.approx.ftz.f32 %0, %1;" : "=f"(y) : "f"(x)); return y;
}

__global__ void __launch_bounds__(THREADS)
gnf_kernel(const float* __restrict__ coords,     // [B, A, 3] f32
           const int*   __restrict__ types_raw,  // [B, A] int32 OR int64 (detected)
           const float* __restrict__ query,      // [B, P, 3] f32
           float*       __restrict__ out)        // [B, P, T, 3] f32
{
    __shared__ float4 satoms[AA];       // type-sorted, scaled coords
    __shared__ int    sStart[TT + 1];
    __shared__ int    sCnt[TT];
    __shared__ int    sOffs[TT];

    const int tid = threadIdx.x;
    const int b   = blockIdx.y;

    // ---- dtype detection: int64 iff every odd 32-bit word in the (safe,
    // valid under both interpretations) first 2048 words is 0 or -1
    if (tid < TT) sCnt[tid] = 0;
    bool ok = true;
    #pragma unroll 4
    for (int i = tid; i < (BB * AA) / 2; i += THREADS) {
        int w = types_raw[2 * i + 1];
        if (w != 0 && w != -1) ok = false;
    }
    const int is64 = __syncthreads_and(ok ? 1 : 0);  // also a full barrier

    // ---- counting sort of this batch's atoms by type (all 128 threads)
    int t_mine = -1;
    {
        long long tv;
        if (is64) tv = ((const long long*)types_raw)[(long)b * AA + tid];
        else      tv = (long long)types_raw[(long)b * AA + tid];
        if (tv >= 0 && tv < TT) {
            t_mine = (int)tv;
            atomicAdd(&sCnt[t_mine], 1);
        }
    }
    __syncthreads();
    if (tid == 0) {
        int s = 0;
        #pragma unroll
        for (int k = 0; k < TT; k++) { sStart[k] = s; sOffs[k] = s; s += sCnt[k]; }
        sStart[TT] = s;
    }
    __syncthreads();
    if (t_mine >= 0) {
        int pos = atomicAdd(&sOffs[t_mine], 1);
        const float* c = coords + ((long)b * AA + tid) * 3;
        satoms[pos] = make_float4(c[0] * K_LOG2E, c[1] * K_LOG2E, c[2] * K_LOG2E, 0.f);
    }
    __syncthreads();

    // ---- per-thread: 2 query points (q0 = base+tid, q1 = base+tid+128)
    const int q0 = blockIdx.x * QPB + tid;
    const float* qp0 = query + ((long)b * PP + q0) * 3;
    const float* qp1 = qp0 + THREADS * 3;
    const float q0x = qp0[0] * K_LOG2E, q0y = qp0[1] * K_LOG2E, q0z = qp0[2] * K_LOG2E;
    const float q1x = qp1[0] * K_LOG2E, q1y = qp1[1] * K_LOG2E, q1z = qp1[2] * K_LOG2E;

    float* outp0 = out + ((long)b * PP + q0) * (TT * 3);
    float* outp1 = outp0 + (long)THREADS * (TT * 3);

    #pragma unroll
    for (int t = 0; t < TT; t++) {
        const int s = sStart[t], e = sStart[t + 1];
        float S0 = 0.f, Gx0 = 0.f, Gy0 = 0.f, Gz0 = 0.f;
        float S1 = 0.f, Gx1 = 0.f, Gy1 = 0.f, Gz1 = 0.f;

        #pragma unroll 2
        for (int i = s; i < e; i++) {
            const float4 c = satoms[i];

            float dx0 = c.x - q0x, dy0 = c.y - q0y, dz0 = c.z - q0z;
            float d20 = fmaf(dx0, dx0, fmaf(dy0, dy0, dz0 * dz0));
            float w0  = ex2f_a(-sqrtf_a(d20));
            S0 += w0;
            Gx0 = fmaf(w0, dx0, Gx0);
            Gy0 = fmaf(w0, dy0, Gy0);
            Gz0 = fmaf(w0, dz0, Gz0);

            float dx1 = c.x - q1x, dy1 = c.y - q1y, dz1 = c.z - q1z;
            float d21 = fmaf(dx1, dx1, fmaf(dy1, dy1, dz1 * dz1));
            float w1  = ex2f_a(-sqrtf_a(d21));
            S1 += w1;
            Gx1 = fmaf(w1, dx1, Gx1);
            Gy1 = fmaf(w1, dy1, Gy1);
            Gz1 = fmaf(w1, dz1, Gz1);
        }

        // finalize: grad = (G/S)/log2(e); clip to norm 0.3; empty type -> 0
        {
            float inv = (S0 > 0.f) ? rcpf_a(S0) * LN2F : 0.f;
            float gx = Gx0 * inv, gy = Gy0 * inv, gz = Gz0 * inv;
            float m2 = fmaf(gx, gx, fmaf(gy, gy, gz * gz));
            if (m2 > CLIP * CLIP) {
                float sc = CLIP * rsqrtf_a(m2);
                gx *= sc; gy *= sc; gz *= sc;
            }
            outp0[t * 3 + 0] = gx; outp0[t * 3 + 1] = gy; outp0[t * 3 + 2] = gz;
        }
        {
            float inv = (S1 > 0.f) ? rcpf_a(S1) * LN2F : 0.f;
            float gx = Gx1 * inv, gy = Gy1 * inv, gz = Gz1 * inv;
            float m2 = fmaf(gx, gx, fmaf(gy, gy, gz * gz));
            if (m2 > CLIP * CLIP) {
                float sc = CLIP * rsqrtf_a(m2);
                gx *= sc; gy *= sc; gz *= sc;
            }
            outp1[t * 3 + 0] = gx; outp1[t * 3 + 1] = gy; outp1[t * 3 + 2] = gz;
        }
    }
}

extern "C" void kernel_launch(void* const* d_in, const int* in_sizes, int n_in,
                              void* d_out, int out_size)
{
    const float* coords = (const float*)d_in[0];   // [16,128,3] f32
    const int*   types  = (const int*)d_in[1];     // [16,128] int32/int64 (detected on device)
    const float* query  = (const float*)d_in[2];   // [16,8192,3] f32
    float*       out    = (float*)d_out;           // [16,8192,5,3] f32

    dim3 grid(PP / QPB, BB);   // (32, 16) = 512 blocks
    gnf_kernel<<<grid, THREADS>>>(coords, types, query, out);
}

// round 3
// speedup vs baseline: 1.0645x; 1.0645x over previous
#include <cuda_runtime.h>

// Problem constants (from reference)
#define BB 16
#define AA 128
#define PP 8192
#define TT 5
#define K_LOG2E 1.4426950408889634f   // log2(e); TEMPERATURE = 1.0
#define LN2F    0.6931471805599453f
#define CLIP    0.3f

#define THREADS 256          // 8 warps/block
#define QPB THREADS          // 1 query per thread

__device__ __forceinline__ float ex2f_a(float x) {
    float y; asm("ex2.approx.ftz.f32 %0, %1;" : "=f"(y) : "f"(x)); return y;
}
__device__ __forceinline__ float sqrtf_a(float x) {
    float y; asm("sqrt.approx.ftz.f32 %0, %1;" : "=f"(y) : "f"(x)); return y;
}
__device__ __forceinline__ float rcpf_a(float x) {
    float y; asm("rcp.approx.ftz.f32 %0, %1;" : "=f"(y) : "f"(x)); return y;
}
__device__ __forceinline__ float rsqrtf_a(float x) {
    float y; asm("rsqrt.approx.ftz.f32 %0, %1;" : "=f"(y) : "f"(x)); return y;
}

__global__ void __launch_bounds__(THREADS)
gnf_kernel(const float* __restrict__ coords,     // [B, A, 3] f32
           const int*   __restrict__ types_raw,  // [B, A] int32 OR int64 (detected)
           const float* __restrict__ query,      // [B, P, 3] f32
           float*       __restrict__ out)        // [B, P, T, 3] f32
{
    __shared__ float4 satoms[AA];       // type-sorted, scaled coords
    __shared__ int    sStart[TT + 1];
    __shared__ int    sCnt[TT];
    __shared__ int    sOffs[TT];

    const int tid = threadIdx.x;
    const int b   = blockIdx.y;

    // ---- dtype detection: int64 iff every odd 32-bit word of the buffer
    // (valid size under both interpretations) is 0 or -1
    if (tid < TT) sCnt[tid] = 0;
    bool ok = true;
    #pragma unroll 2
    for (int i = tid; i < (BB * AA) / 2; i += THREADS) {
        int w = types_raw[2 * i + 1];
        if (w != 0 && w != -1) ok = false;
    }
    const int is64 = __syncthreads_and(ok ? 1 : 0);  // also a full barrier

    // ---- counting sort of this batch's 128 atoms by type (threads 0..127)
    int t_mine = -1;
    if (tid < AA) {
        long long tv;
        if (is64) tv = ((const long long*)types_raw)[(long)b * AA + tid];
        else      tv = (long long)types_raw[(long)b * AA + tid];
        if (tv >= 0 && tv < TT) {
            t_mine = (int)tv;
            atomicAdd(&sCnt[t_mine], 1);
        }
    }
    __syncthreads();
    if (tid == 0) {
        int s = 0;
        #pragma unroll
        for (int k = 0; k < TT; k++) { sStart[k] = s; sOffs[k] = s; s += sCnt[k]; }
        sStart[TT] = s;
    }
    __syncthreads();
    if (t_mine >= 0) {
        int pos = atomicAdd(&sOffs[t_mine], 1);
        const float* c = coords + ((long)b * AA + tid) * 3;
        satoms[pos] = make_float4(c[0] * K_LOG2E, c[1] * K_LOG2E, c[2] * K_LOG2E, 0.f);
    }
    __syncthreads();

    // ---- one query point per thread
    const int q0 = blockIdx.x * QPB + tid;
    const float* qp = query + ((long)b * PP + q0) * 3;
    const float qx = qp[0] * K_LOG2E, qy = qp[1] * K_LOG2E, qz = qp[2] * K_LOG2E;

    float* outp = out + ((long)b * PP + q0) * (TT * 3);

    #pragma unroll
    for (int t = 0; t < TT; t++) {
        const int s = sStart[t], e = sStart[t + 1];
        float S0 = 0.f, Gx0 = 0.f, Gy0 = 0.f, Gz0 = 0.f;
        float S1 = 0.f, Gx1 = 0.f, Gy1 = 0.f, Gz1 = 0.f;

        int i = s;
        // unroll-by-2: two independent sqrt->ex2 chains in flight per thread
        for (; i + 1 < e; i += 2) {
            const float4 c0 = satoms[i];
            const float4 c1 = satoms[i + 1];

            float dx0 = c0.x - qx, dy0 = c0.y - qy, dz0 = c0.z - qz;
            float dx1 = c1.x - qx, dy1 = c1.y - qy, dz1 = c1.z - qz;

            float d20 = fmaf(dx0, dx0, fmaf(dy0, dy0, dz0 * dz0));
            float d21 = fmaf(dx1, dx1, fmaf(dy1, dy1, dz1 * dz1));

            float w0 = ex2f_a(-sqrtf_a(d20));
            float w1 = ex2f_a(-sqrtf_a(d21));

            S0 += w0;
            Gx0 = fmaf(w0, dx0, Gx0);
            Gy0 = fmaf(w0, dy0, Gy0);
            Gz0 = fmaf(w0, dz0, Gz0);

            S1 += w1;
            Gx1 = fmaf(w1, dx1, Gx1);
            Gy1 = fmaf(w1, dy1, Gy1);
            Gz1 = fmaf(w1, dz1, Gz1);
        }
        if (i < e) {
            const float4 c0 = satoms[i];
            float dx0 = c0.x - qx, dy0 = c0.y - qy, dz0 = c0.z - qz;
            float d20 = fmaf(dx0, dx0, fmaf(dy0, dy0, dz0 * dz0));
            float w0 = ex2f_a(-sqrtf_a(d20));
            S0 += w0;
            Gx0 = fmaf(w0, dx0, Gx0);
            Gy0 = fmaf(w0, dy0, Gy0);
            Gz0 = fmaf(w0, dz0, Gz0);
        }

        float S = S0 + S1;
        float Gx = Gx0 + Gx1, Gy = Gy0 + Gy1, Gz = Gz0 + Gz1;

        // finalize: grad = (G/S)/log2(e); clip to norm 0.3; empty type -> 0
        float inv = (S > 0.f) ? rcpf_a(S) * LN2F : 0.f;
        float gx = Gx * inv, gy = Gy * inv, gz = Gz * inv;
        float m2 = fmaf(gx, gx, fmaf(gy, gy, gz * gz));
        if (m2 > CLIP * CLIP) {
            float sc = CLIP * rsqrtf_a(m2);
            gx *= sc; gy *= sc; gz *= sc;
        }
        outp[t * 3 + 0] = gx; outp[t * 3 + 1] = gy; outp[t * 3 + 2] = gz;
    }
}

extern "C" void kernel_launch(void* const* d_in, const int* in_sizes, int n_in,
                              void* d_out, int out_size)
{
    const float* coords = (const float*)d_in[0];   // [16,128,3] f32
    const int*   types  = (const int*)d_in[1];     // [16,128] int32/int64 (detected on device)
    const float* query  = (const float*)d_in[2];   // [16,8192,3] f32
    float*       out    = (float*)d_out;           // [16,8192,5,3] f32

    dim3 grid(PP / QPB, BB);   // (32, 16) = 512 blocks x 256 threads
    gnf_kernel<<<grid, THREADS>>>(coords, types, query, out);
}